// round 9
// baseline (speedup 1.0000x reference)
#include <cuda_runtime.h>
#include <cuda_bf16.h>
#include <cstdint>

// LSTMBaseline: 2-layer LSTM (B=2048, T=512, H=128, in=2) + MLP head -> [B,2]
// bf16 mma.m16n8k16, 128 CTAs x 512 thr, M=16 batch rows/CTA.
// Round 9 = Round 5 winner + L1C 3->2 (frees L1D) + prefetch.global.L1 of
// streamed weight chunks 2 ahead (zero register cost). Streamed LDGs then
// hit L1 (~39cyc) instead of L2 (~234cyc).

#define T_STEPS 512
#define HID     128
#define MROWS   16
#define NCTA    128
#define NTHR    512
#define HSTR    76            // h-row stride in bf16-pairs; ldmatrix conflict-free
#define PB      (MROWS * HSTR * 4)   // phase stride in bytes

#define L0KP    9             // layer0 k-chunks (128 h + xr,xg + pad)
#define L1KP    16            // layer1 k-chunks (128 h0 | 128 h1)
#define L1C     2             // layer1 k-chunks cached in smem
#define NSTREAM (L1KP - L1C)  // 14 streamed k-chunks

// uint4 = {gtA.b0, gtA.b1, gtB.b0, gtB.b1}, gtA=2p, gtB=2p+1
// index: ((w*KP + kp)*2 + p)*32 + lane
__device__ uint4 d_WB0u[16 * L0KP * 2 * 32];   // 147456 B
__device__ uint4 d_WB1u[16 * L1KP * 2 * 32];   // 262144 B
__device__ float d_B0[512];
__device__ float d_B1[512];

#define PF_L1(p) asm volatile("prefetch.global.L1 [%0];" :: "l"(p))

__device__ __forceinline__ uint32_t pack_bf2(float a, float b)
{
    __nv_bfloat162 p = __floats2bfloat162_rn(a, b);
    return *reinterpret_cast<uint32_t*>(&p);
}

__device__ __forceinline__ float wval0(const float* w_hh0, const float* w_ih0,
                                       int g, int kp, int c, int q)
{
    int k = kp * 16 + (q >> 1) * 8 + c * 2 + (q & 1);
    if (k < 128)  return w_hh0[g * 128 + k];
    if (k == 128) return w_ih0[g * 2 + 0];
    if (k == 129) return w_ih0[g * 2 + 1];
    return 0.f;
}

__global__ void prep_kernel(const float* __restrict__ w_hh0, const float* __restrict__ w_ih0,
                            const float* __restrict__ b_ih0, const float* __restrict__ b_hh0,
                            const float* __restrict__ w_ih1, const float* __restrict__ w_hh1,
                            const float* __restrict__ b_ih1, const float* __restrict__ b_hh1)
{
    int idx = blockIdx.x * blockDim.x + threadIdx.x;
    int l = idx & 31, c = l & 3;
    int r = idx >> 5;

    if (idx < 16 * L0KP * 2 * 32) {           // ---- WB0 ----
        int p = r & 1, rr = r >> 1;
        int kp = rr % L0KP, w = rr / L0KP;
        int n = w * 8 + (l >> 2);
        int gA = (2 * p) * 128 + n, gB = (2 * p + 1) * 128 + n;
        d_WB0u[idx] = make_uint4(
            pack_bf2(wval0(w_hh0, w_ih0, gA, kp, c, 0), wval0(w_hh0, w_ih0, gA, kp, c, 1)),
            pack_bf2(wval0(w_hh0, w_ih0, gA, kp, c, 2), wval0(w_hh0, w_ih0, gA, kp, c, 3)),
            pack_bf2(wval0(w_hh0, w_ih0, gB, kp, c, 0), wval0(w_hh0, w_ih0, gB, kp, c, 1)),
            pack_bf2(wval0(w_hh0, w_ih0, gB, kp, c, 2), wval0(w_hh0, w_ih0, gB, kp, c, 3)));
    }
    if (idx < 16 * L1KP * 2 * 32) {           // ---- WB1 ----
        int p = r & 1, rr = r >> 1;
        int kp = rr % L1KP, w = rr / L1KP;
        int n = w * 8 + (l >> 2);
        const float* src = (kp < 8) ? w_ih1 : w_hh1;
        float v[2][4];
#pragma unroll
        for (int j = 0; j < 2; j++) {
            int g = (2 * p + j) * 128 + n;
#pragma unroll
            for (int q = 0; q < 4; q++) {
                int kk = (kp & 7) * 16 + (q >> 1) * 8 + c * 2 + (q & 1);
                v[j][q] = src[g * 128 + kk];
            }
        }
        d_WB1u[idx] = make_uint4(
            pack_bf2(v[0][0], v[0][1]), pack_bf2(v[0][2], v[0][3]),
            pack_bf2(v[1][0], v[1][1]), pack_bf2(v[1][2], v[1][3]));
    }
    if (idx < 512) {
        d_B0[idx] = b_ih0[idx] + b_hh0[idx];
        d_B1[idx] = b_ih1[idx] + b_hh1[idx];
    }
}

__device__ __forceinline__ void mma16(float acc[4], uint32_t a0, uint32_t a1,
                                      uint32_t a2, uint32_t a3, uint32_t b0, uint32_t b1)
{
    asm volatile(
        "mma.sync.aligned.m16n8k16.row.col.f32.bf16.bf16.f32 "
        "{%0,%1,%2,%3}, {%4,%5,%6,%7}, {%8,%9}, {%0,%1,%2,%3};\n"
        : "+f"(acc[0]), "+f"(acc[1]), "+f"(acc[2]), "+f"(acc[3])
        : "r"(a0), "r"(a1), "r"(a2), "r"(a3), "r"(b0), "r"(b1));
}

#define LDSM4(a0, a1, a2, a3, addr)                                       \
    asm volatile("ldmatrix.sync.aligned.m8n8.x4.shared.b16 "              \
                 "{%0,%1,%2,%3}, [%4];"                                   \
                 : "=r"(a0), "=r"(a1), "=r"(a2), "=r"(a3) : "r"(addr))

__device__ __forceinline__ float tanha(float x)
{
    float y;
    asm("tanh.approx.f32 %0, %1;" : "=f"(y) : "f"(x));
    return y;
}
__device__ __forceinline__ float sigf(float x)
{
    return fmaf(tanha(0.5f * x), 0.5f, 0.5f);
}

__device__ __forceinline__ void mma4(float acc[4][4], uint32_t a0, uint32_t a1,
                                     uint32_t a2, uint32_t a3, uint4 w01, uint4 w23)
{
    mma16(acc[0], a0, a1, a2, a3, w01.x, w01.y);
    mma16(acc[1], a0, a1, a2, a3, w01.z, w01.w);
    mma16(acc[2], a0, a1, a2, a3, w23.x, w23.y);
    mma16(acc[3], a0, a1, a2, a3, w23.z, w23.w);
}

__device__ __forceinline__ void acc_init(float acc[4][4], const float* bs)
{
#pragma unroll
    for (int gt = 0; gt < 4; gt++) {
        acc[gt][0] = bs[gt * 2];  acc[gt][1] = bs[gt * 2 + 1];
        acc[gt][2] = bs[gt * 2];  acc[gt][3] = bs[gt * 2 + 1];
    }
}

__device__ __forceinline__ void cell(const float acc[4][4], float* cs,
                                     uint32_t* __restrict__ hdst, int r0, int c0, int w)
{
#pragma unroll
    for (int rg = 0; rg < 2; rg++) {
        float hv[2];
#pragma unroll
        for (int j = 0; j < 2; j++) {
            int idx = rg * 2 + j;
            float i_ = sigf(acc[0][idx]);
            float f_ = sigf(acc[1][idx]);
            float g_ = tanha(acc[2][idx]);
            float o_ = sigf(acc[3][idx]);
            float cv = fmaf(f_, cs[idx], i_ * g_);
            cs[idx] = cv;
            hv[j] = o_ * tanha(cv);
        }
        hdst[(r0 + 8 * rg) * HSTR + w * 4 + c0] = pack_bf2(hv[0], hv[1]);
    }
}

#define SW0_U4 (16 * L0KP * 2 * 32)           // 9216 uint4  = 147456 B
#define SW1_U4 (16 * L1C * 2 * 32)            // 2048 uint4  = 32768 B
#define HBUF   (2 * MROWS * HSTR)             // uint32 per layer ping-pong pair
#define SMEM_SZ (SW0_U4 * 16 + SW1_U4 * 16 + 2 * HBUF * 4)   // 199680 B

__global__ void __launch_bounds__(NTHR, 1)
lstm_main(const float* __restrict__ hr, const float* __restrict__ glu,
          const float* __restrict__ w1, const float* __restrict__ b1,
          const float* __restrict__ w2, const float* __restrict__ b2,
          float* __restrict__ out)
{
    extern __shared__ char smem_raw[];
    uint4*    sw0 = reinterpret_cast<uint4*>(smem_raw);
    uint4*    sw1 = reinterpret_cast<uint4*>(smem_raw + SW0_U4 * 16);
    uint32_t* h0e = reinterpret_cast<uint32_t*>(smem_raw + SW0_U4 * 16 + SW1_U4 * 16);
    uint32_t* h1e = h0e + HBUF;
    float*    hid_s = reinterpret_cast<float*>(smem_raw);   // overlay after loop

    const int tid = threadIdx.x;
    const int l = tid & 31, w = tid >> 5;
    const int r0 = l >> 2, c0 = l & 3;
    const int B0 = blockIdx.x * MROWS;

    // ---- load resident weights ----
    for (int i = tid; i < SW0_U4; i += NTHR) sw0[i] = d_WB0u[i];
    for (int i = tid; i < SW1_U4; i += NTHR) {
        int ll = i & 31, r = i >> 5;
        int p = r & 1, rr = r >> 1;
        int kp = rr % L1C, ww = rr / L1C;
        sw1[i] = d_WB1u[((ww * L1KP + kp) * 2 + p) * 32 + ll];
    }
    for (int i = tid; i < HBUF; i += NTHR) { h0e[i] = 0u; h1e[i] = 0u; }
    __syncthreads();
    if (tid < MROWS)    // x_0 -> pair 64 of h0e phase 0
        h0e[tid * HSTR + 64] = pack_bf2(hr[(B0 + tid) * T_STEPS], glu[(B0 + tid) * T_STEPS]);

    float bs0[8], bs1[8];
#pragma unroll
    for (int gt = 0; gt < 4; gt++)
#pragma unroll
        for (int j = 0; j < 2; j++) {
            int g = gt * 128 + w * 8 + 2 * c0 + j;
            bs0[gt * 2 + j] = d_B0[g];
            bs1[gt * 2 + j] = d_B1[g];
        }

    float cs0[4] = {0.f, 0.f, 0.f, 0.f};
    float cs1[4] = {0.f, 0.f, 0.f, 0.f};

    // per-thread ldmatrix address offset
    const uint32_t aoff = (uint32_t)((l & 15) * (HSTR * 4) + ((l >> 4) << 4));
    const uint32_t h0u = (uint32_t)__cvta_generic_to_shared(h0e) + aoff;
    const uint32_t h1u = (uint32_t)__cvta_generic_to_shared(h1e) + aoff;

    const uint4* ws0 = sw0 + (w * L0KP) * 64 + l;             // [kp*64 + p*32]
    const uint4* ws1 = sw1 + (w * L1C) * 64 + l;
    const uint4* wg1 = d_WB1u + ((w * L1KP + L1C) * 2) * 32 + l;   // streamed s: [s*64 + p*32]

    __syncthreads();

    // ---- prologue: h0_0 from [h0=0, x_0] ----
    {
        float acc0[4][4];
        acc_init(acc0, bs0);
#pragma unroll
        for (int kp = 0; kp < L0KP; kp++) {
            uint32_t a0, a1, a2, a3;
            LDSM4(a0, a1, a2, a3, h0u + kp * 32);
            mma4(acc0, a0, a1, a2, a3, ws0[kp * 64], ws0[kp * 64 + 32]);
        }
        cell(acc0, cs0, h0e + MROWS * HSTR, r0, c0, w);
        if (tid < MROWS)
            h0e[MROWS * HSTR + tid * HSTR + 64] =
                pack_bf2(hr[(B0 + tid) * T_STEPS + 1], glu[(B0 + tid) * T_STEPS + 1]);
        // warm L1 for the first step's early streamed chunks
        PF_L1(wg1);  PF_L1(wg1 + 32);
        PF_L1(wg1 + 64);  PF_L1(wg1 + 96);
        __syncthreads();
    }

    int cur = 1;
#pragma unroll 1
    for (int t = 0; t < T_STEPS; t++) {
        const int nxt = cur ^ 1;
        const uint32_t h0b = h0u + cur * PB;      // h0_t (+ x_{t+1})
        const uint32_t h1b = h1u + cur * PB;      // h1_{t-1}
        float acc1[4][4], acc0[4][4];
        acc_init(acc1, bs1);
        acc_init(acc0, bs0);

        uint4 Wc0 = __ldg(wg1), Wc1 = __ldg(wg1 + 32);

        // ---- merged h0 pass: layer1 (kp<8) + layer0 (all 9 kp) ----
#pragma unroll
        for (int kp = 0; kp < L0KP; kp++) {
            uint32_t a0, a1, a2, a3;
            LDSM4(a0, a1, a2, a3, h0b + kp * 32);
            if (kp < 8) {
                if (kp < L1C) {
                    mma4(acc1, a0, a1, a2, a3, ws1[kp * 64], ws1[kp * 64 + 32]);
                } else {
                    uint4 w01 = Wc0, w23 = Wc1;
                    int s = kp - L1C;                       // 0..5
                    Wc0 = __ldg(wg1 + (s + 1) * 64);
                    Wc1 = __ldg(wg1 + (s + 1) * 64 + 32);
                    // prefetch s+2 into L1 (2..7, always < NSTREAM)
                    PF_L1(wg1 + (s + 2) * 64);
                    PF_L1(wg1 + (s + 2) * 64 + 32);
                    mma4(acc1, a0, a1, a2, a3, w01, w23);
                }
            }
            mma4(acc0, a0, a1, a2, a3, ws0[kp * 64], ws0[kp * 64 + 32]);
        }

        // ---- cell0 (MUFU) issues under the h1-part tensor stream ----
        cell(acc0, cs0, h0e + nxt * MROWS * HSTR, r0, c0, w);   // h0_{t+1}
        if (tid < MROWS && t + 2 < T_STEPS)
            h0e[nxt * MROWS * HSTR + tid * HSTR + 64] =
                pack_bf2(hr[(B0 + tid) * T_STEPS + t + 2],
                         glu[(B0 + tid) * T_STEPS + t + 2]);

        // ---- h1 pass: layer1 kp 8..15 (streamed s = 6..13) ----
#pragma unroll
        for (int kp = 0; kp < 8; kp++) {
            uint32_t a0, a1, a2, a3;
            LDSM4(a0, a1, a2, a3, h1b + kp * 32);
            uint4 w01 = Wc0, w23 = Wc1;
            int s = 6 + kp;
            if (s + 1 < NSTREAM) {
                Wc0 = __ldg(wg1 + (s + 1) * 64);
                Wc1 = __ldg(wg1 + (s + 1) * 64 + 32);
            }
            // prefetch s+2; wrap to next step's s=0,1 at the tail
            int sp = s + 2;
            const uint4* pf = wg1 + ((sp < NSTREAM) ? sp : (sp - NSTREAM)) * 64;
            PF_L1(pf);
            PF_L1(pf + 32);
            mma4(acc1, a0, a1, a2, a3, w01, w23);
        }

        cell(acc1, cs1, h1e + nxt * MROWS * HSTR, r0, c0, w);   // h1_t

        __syncthreads();
        cur = nxt;
    }
    // final h1_511 in h1e phase cur; smem weights now dead.

    // ---- head: hidden = relu(h1 @ w1^T + b1) ----
    if (tid < 256) {
        int ff = tid & 63;
        int mq = tid >> 6;
        const float2* w1p = reinterpret_cast<const float2*>(w1 + ff * HID);
#pragma unroll
        for (int j = 0; j < 4; j++) {
            int m = mq + j * 4;
            float s = b1[ff];
            const uint32_t* hp = h1e + cur * MROWS * HSTR + m * HSTR;
#pragma unroll 8
            for (int p = 0; p < 64; p++) {
                float2 hv = __bfloat1622float2(
                    *reinterpret_cast<const __nv_bfloat162*>(&hp[p]));
                float2 wv = w1p[p];
                s = fmaf(hv.x, wv.x, s);
                s = fmaf(hv.y, wv.y, s);
            }
            hid_s[m * 64 + ff] = fmaxf(s, 0.f);
        }
    }
    __syncthreads();

    // ---- head: out = hidden @ w2^T + b2 ----
    if (tid < 32) {
        int m = tid >> 1, o = tid & 1;
        float s = b2[o];
#pragma unroll 8
        for (int k = 0; k < 64; k++)
            s = fmaf(hid_s[m * 64 + k], w2[o * 64 + k], s);
        out[(B0 + m) * 2 + o] = s;
    }
}

extern "C" void kernel_launch(void* const* d_in, const int* in_sizes, int n_in,
                              void* d_out, int out_size)
{
    const float* hr   = (const float*)d_in[0];
    const float* glu  = (const float*)d_in[1];
    const float* wih0 = (const float*)d_in[2];
    const float* whh0 = (const float*)d_in[3];
    const float* bih0 = (const float*)d_in[4];
    const float* bhh0 = (const float*)d_in[5];
    const float* wih1 = (const float*)d_in[6];
    const float* whh1 = (const float*)d_in[7];
    const float* bih1 = (const float*)d_in[8];
    const float* bhh1 = (const float*)d_in[9];
    const float* w1   = (const float*)d_in[10];
    const float* b1   = (const float*)d_in[11];
    const float* w2   = (const float*)d_in[12];
    const float* b2   = (const float*)d_in[13];
    float* out = (float*)d_out;

    cudaFuncSetAttribute(lstm_main, cudaFuncAttributeMaxDynamicSharedMemorySize, SMEM_SZ);

    prep_kernel<<<128, 256>>>(whh0, wih0, bih0, bhh0, wih1, whh1, bih1, bhh1);
    lstm_main<<<NCTA, NTHR, SMEM_SZ>>>(hr, glu, w1, b1, w2, b2, out);
}

// round 10
// speedup vs baseline: 1.7738x; 1.7738x over previous
#include <cuda_runtime.h>
#include <cuda_bf16.h>
#include <cstdint>

// LSTMBaseline: 2-layer LSTM (B=2048, T=512, H=128, in=2) + MLP head -> [B,2]
// bf16 mma.m16n8k16, 128 CTAs x 512 thr, M=16 batch rows/CTA.
// Round 10 = Round 5 winner with ONE constant change: L1C 3 -> 4 (one more
// loop-invariant layer-1 weight chunk resident in smem; dynamic smem at the
// 227KB opt-in ceiling). Identical instruction schedule otherwise.

#define T_STEPS 512
#define HID     128
#define MROWS   16
#define NCTA    128
#define NTHR    512
#define HSTR    76            // h-row stride in bf16-pairs; ldmatrix conflict-free
#define PB      (MROWS * HSTR * 4)   // phase stride in bytes

#define L0KP    9             // layer0 k-chunks (128 h + xr,xg + pad)
#define L1KP    16            // layer1 k-chunks (128 h0 | 128 h1)
#define L1C     4             // layer1 k-chunks cached in smem
#define NSTREAM (L1KP - L1C)  // 12 streamed k-chunks

// uint4 = {gtA.b0, gtA.b1, gtB.b0, gtB.b1}, gtA=2p, gtB=2p+1
// index: ((w*KP + kp)*2 + p)*32 + lane
__device__ uint4 d_WB0u[16 * L0KP * 2 * 32];   // 147456 B
__device__ uint4 d_WB1u[16 * L1KP * 2 * 32];   // 262144 B
__device__ float d_B0[512];
__device__ float d_B1[512];

__device__ __forceinline__ uint32_t pack_bf2(float a, float b)
{
    __nv_bfloat162 p = __floats2bfloat162_rn(a, b);
    return *reinterpret_cast<uint32_t*>(&p);
}

__device__ __forceinline__ float wval0(const float* w_hh0, const float* w_ih0,
                                       int g, int kp, int c, int q)
{
    int k = kp * 16 + (q >> 1) * 8 + c * 2 + (q & 1);
    if (k < 128)  return w_hh0[g * 128 + k];
    if (k == 128) return w_ih0[g * 2 + 0];
    if (k == 129) return w_ih0[g * 2 + 1];
    return 0.f;
}

__global__ void prep_kernel(const float* __restrict__ w_hh0, const float* __restrict__ w_ih0,
                            const float* __restrict__ b_ih0, const float* __restrict__ b_hh0,
                            const float* __restrict__ w_ih1, const float* __restrict__ w_hh1,
                            const float* __restrict__ b_ih1, const float* __restrict__ b_hh1)
{
    int idx = blockIdx.x * blockDim.x + threadIdx.x;
    int l = idx & 31, c = l & 3;
    int r = idx >> 5;

    if (idx < 16 * L0KP * 2 * 32) {           // ---- WB0 ----
        int p = r & 1, rr = r >> 1;
        int kp = rr % L0KP, w = rr / L0KP;
        int n = w * 8 + (l >> 2);
        int gA = (2 * p) * 128 + n, gB = (2 * p + 1) * 128 + n;
        d_WB0u[idx] = make_uint4(
            pack_bf2(wval0(w_hh0, w_ih0, gA, kp, c, 0), wval0(w_hh0, w_ih0, gA, kp, c, 1)),
            pack_bf2(wval0(w_hh0, w_ih0, gA, kp, c, 2), wval0(w_hh0, w_ih0, gA, kp, c, 3)),
            pack_bf2(wval0(w_hh0, w_ih0, gB, kp, c, 0), wval0(w_hh0, w_ih0, gB, kp, c, 1)),
            pack_bf2(wval0(w_hh0, w_ih0, gB, kp, c, 2), wval0(w_hh0, w_ih0, gB, kp, c, 3)));
    }
    if (idx < 16 * L1KP * 2 * 32) {           // ---- WB1 ----
        int p = r & 1, rr = r >> 1;
        int kp = rr % L1KP, w = rr / L1KP;
        int n = w * 8 + (l >> 2);
        const float* src = (kp < 8) ? w_ih1 : w_hh1;
        float v[2][4];
#pragma unroll
        for (int j = 0; j < 2; j++) {
            int g = (2 * p + j) * 128 + n;
#pragma unroll
            for (int q = 0; q < 4; q++) {
                int kk = (kp & 7) * 16 + (q >> 1) * 8 + c * 2 + (q & 1);
                v[j][q] = src[g * 128 + kk];
            }
        }
        d_WB1u[idx] = make_uint4(
            pack_bf2(v[0][0], v[0][1]), pack_bf2(v[0][2], v[0][3]),
            pack_bf2(v[1][0], v[1][1]), pack_bf2(v[1][2], v[1][3]));
    }
    if (idx < 512) {
        d_B0[idx] = b_ih0[idx] + b_hh0[idx];
        d_B1[idx] = b_ih1[idx] + b_hh1[idx];
    }
}

__device__ __forceinline__ void mma16(float acc[4], uint32_t a0, uint32_t a1,
                                      uint32_t a2, uint32_t a3, uint32_t b0, uint32_t b1)
{
    asm volatile(
        "mma.sync.aligned.m16n8k16.row.col.f32.bf16.bf16.f32 "
        "{%0,%1,%2,%3}, {%4,%5,%6,%7}, {%8,%9}, {%0,%1,%2,%3};\n"
        : "+f"(acc[0]), "+f"(acc[1]), "+f"(acc[2]), "+f"(acc[3])
        : "r"(a0), "r"(a1), "r"(a2), "r"(a3), "r"(b0), "r"(b1));
}

#define LDSM4(a0, a1, a2, a3, addr)                                       \
    asm volatile("ldmatrix.sync.aligned.m8n8.x4.shared.b16 "              \
                 "{%0,%1,%2,%3}, [%4];"                                   \
                 : "=r"(a0), "=r"(a1), "=r"(a2), "=r"(a3) : "r"(addr))

__device__ __forceinline__ float tanha(float x)
{
    float y;
    asm("tanh.approx.f32 %0, %1;" : "=f"(y) : "f"(x));
    return y;
}
__device__ __forceinline__ float sigf(float x)
{
    return fmaf(tanha(0.5f * x), 0.5f, 0.5f);
}

__device__ __forceinline__ void mma4(float acc[4][4], uint32_t a0, uint32_t a1,
                                     uint32_t a2, uint32_t a3, uint4 w01, uint4 w23)
{
    mma16(acc[0], a0, a1, a2, a3, w01.x, w01.y);
    mma16(acc[1], a0, a1, a2, a3, w01.z, w01.w);
    mma16(acc[2], a0, a1, a2, a3, w23.x, w23.y);
    mma16(acc[3], a0, a1, a2, a3, w23.z, w23.w);
}

__device__ __forceinline__ void acc_init(float acc[4][4], const float* bs)
{
#pragma unroll
    for (int gt = 0; gt < 4; gt++) {
        acc[gt][0] = bs[gt * 2];  acc[gt][1] = bs[gt * 2 + 1];
        acc[gt][2] = bs[gt * 2];  acc[gt][3] = bs[gt * 2 + 1];
    }
}

__device__ __forceinline__ void cell(const float acc[4][4], float* cs,
                                     uint32_t* __restrict__ hdst, int r0, int c0, int w)
{
#pragma unroll
    for (int rg = 0; rg < 2; rg++) {
        float hv[2];
#pragma unroll
        for (int j = 0; j < 2; j++) {
            int idx = rg * 2 + j;
            float i_ = sigf(acc[0][idx]);
            float f_ = sigf(acc[1][idx]);
            float g_ = tanha(acc[2][idx]);
            float o_ = sigf(acc[3][idx]);
            float cv = fmaf(f_, cs[idx], i_ * g_);
            cs[idx] = cv;
            hv[j] = o_ * tanha(cv);
        }
        hdst[(r0 + 8 * rg) * HSTR + w * 4 + c0] = pack_bf2(hv[0], hv[1]);
    }
}

#define SW0_U4 (16 * L0KP * 2 * 32)           // 9216 uint4  = 147456 B
#define SW1_U4 (16 * L1C * 2 * 32)            // 4096 uint4  = 65536 B
#define HBUF   (2 * MROWS * HSTR)             // uint32 per layer ping-pong pair
#define SMEM_SZ (SW0_U4 * 16 + SW1_U4 * 16 + 2 * HBUF * 4)   // 232448 B = 227KB

__global__ void __launch_bounds__(NTHR, 1)
lstm_main(const float* __restrict__ hr, const float* __restrict__ glu,
          const float* __restrict__ w1, const float* __restrict__ b1,
          const float* __restrict__ w2, const float* __restrict__ b2,
          float* __restrict__ out)
{
    extern __shared__ char smem_raw[];
    uint4*    sw0 = reinterpret_cast<uint4*>(smem_raw);
    uint4*    sw1 = reinterpret_cast<uint4*>(smem_raw + SW0_U4 * 16);
    uint32_t* h0e = reinterpret_cast<uint32_t*>(smem_raw + SW0_U4 * 16 + SW1_U4 * 16);
    uint32_t* h1e = h0e + HBUF;
    float*    hid_s = reinterpret_cast<float*>(smem_raw);   // overlay after loop

    const int tid = threadIdx.x;
    const int l = tid & 31, w = tid >> 5;
    const int r0 = l >> 2, c0 = l & 3;
    const int B0 = blockIdx.x * MROWS;

    // ---- load resident weights ----
    for (int i = tid; i < SW0_U4; i += NTHR) sw0[i] = d_WB0u[i];
    for (int i = tid; i < SW1_U4; i += NTHR) {
        int ll = i & 31, r = i >> 5;
        int p = r & 1, rr = r >> 1;
        int kp = rr % L1C, ww = rr / L1C;
        sw1[i] = d_WB1u[((ww * L1KP + kp) * 2 + p) * 32 + ll];
    }
    for (int i = tid; i < HBUF; i += NTHR) { h0e[i] = 0u; h1e[i] = 0u; }
    __syncthreads();
    if (tid < MROWS)    // x_0 -> pair 64 of h0e phase 0
        h0e[tid * HSTR + 64] = pack_bf2(hr[(B0 + tid) * T_STEPS], glu[(B0 + tid) * T_STEPS]);

    float bs0[8], bs1[8];
#pragma unroll
    for (int gt = 0; gt < 4; gt++)
#pragma unroll
        for (int j = 0; j < 2; j++) {
            int g = gt * 128 + w * 8 + 2 * c0 + j;
            bs0[gt * 2 + j] = d_B0[g];
            bs1[gt * 2 + j] = d_B1[g];
        }

    float cs0[4] = {0.f, 0.f, 0.f, 0.f};
    float cs1[4] = {0.f, 0.f, 0.f, 0.f};

    // per-thread ldmatrix address offset
    const uint32_t aoff = (uint32_t)((l & 15) * (HSTR * 4) + ((l >> 4) << 4));
    const uint32_t h0u = (uint32_t)__cvta_generic_to_shared(h0e) + aoff;
    const uint32_t h1u = (uint32_t)__cvta_generic_to_shared(h1e) + aoff;

    const uint4* ws0 = sw0 + (w * L0KP) * 64 + l;             // [kp*64 + p*32]
    const uint4* ws1 = sw1 + (w * L1C) * 64 + l;
    const uint4* wg1 = d_WB1u + ((w * L1KP + L1C) * 2) * 32 + l;   // streamed s: [s*64 + p*32]

    __syncthreads();

    // ---- prologue: h0_0 from [h0=0, x_0] ----
    {
        float acc0[4][4];
        acc_init(acc0, bs0);
#pragma unroll
        for (int kp = 0; kp < L0KP; kp++) {
            uint32_t a0, a1, a2, a3;
            LDSM4(a0, a1, a2, a3, h0u + kp * 32);
            mma4(acc0, a0, a1, a2, a3, ws0[kp * 64], ws0[kp * 64 + 32]);
        }
        cell(acc0, cs0, h0e + MROWS * HSTR, r0, c0, w);
        if (tid < MROWS)
            h0e[MROWS * HSTR + tid * HSTR + 64] =
                pack_bf2(hr[(B0 + tid) * T_STEPS + 1], glu[(B0 + tid) * T_STEPS + 1]);
        __syncthreads();
    }

    int cur = 1;
#pragma unroll 1
    for (int t = 0; t < T_STEPS; t++) {
        const int nxt = cur ^ 1;
        const uint32_t h0b = h0u + cur * PB;      // h0_t (+ x_{t+1})
        const uint32_t h1b = h1u + cur * PB;      // h1_{t-1}
        float acc1[4][4], acc0[4][4];
        acc_init(acc1, bs1);
        acc_init(acc0, bs0);

        uint4 Wc0 = __ldg(wg1), Wc1 = __ldg(wg1 + 32);

        // ---- merged h0 pass: layer1 (kp<8) + layer0 (all 9 kp) ----
#pragma unroll
        for (int kp = 0; kp < L0KP; kp++) {
            uint32_t a0, a1, a2, a3;
            LDSM4(a0, a1, a2, a3, h0b + kp * 32);
            if (kp < 8) {
                if (kp < L1C) {
                    mma4(acc1, a0, a1, a2, a3, ws1[kp * 64], ws1[kp * 64 + 32]);
                } else {
                    uint4 w01 = Wc0, w23 = Wc1;
                    int s = kp - L1C;                       // 0..3
                    Wc0 = __ldg(wg1 + (s + 1) * 64);
                    Wc1 = __ldg(wg1 + (s + 1) * 64 + 32);
                    mma4(acc1, a0, a1, a2, a3, w01, w23);
                }
            }
            mma4(acc0, a0, a1, a2, a3, ws0[kp * 64], ws0[kp * 64 + 32]);
        }

        // ---- cell0 (MUFU) issues under the h1-part tensor stream ----
        cell(acc0, cs0, h0e + nxt * MROWS * HSTR, r0, c0, w);   // h0_{t+1}
        if (tid < MROWS && t + 2 < T_STEPS)
            h0e[nxt * MROWS * HSTR + tid * HSTR + 64] =
                pack_bf2(hr[(B0 + tid) * T_STEPS + t + 2],
                         glu[(B0 + tid) * T_STEPS + t + 2]);

        // ---- h1 pass: layer1 kp 8..15 (streamed s = 4..11) ----
#pragma unroll
        for (int kp = 0; kp < 8; kp++) {
            uint32_t a0, a1, a2, a3;
            LDSM4(a0, a1, a2, a3, h1b + kp * 32);
            uint4 w01 = Wc0, w23 = Wc1;
            int s = 4 + kp;
            if (s + 1 < NSTREAM) {
                Wc0 = __ldg(wg1 + (s + 1) * 64);
                Wc1 = __ldg(wg1 + (s + 1) * 64 + 32);
            }
            mma4(acc1, a0, a1, a2, a3, w01, w23);
        }

        cell(acc1, cs1, h1e + nxt * MROWS * HSTR, r0, c0, w);   // h1_t

        __syncthreads();
        cur = nxt;
    }
    // final h1_511 in h1e phase cur; smem weights now dead.

    // ---- head: hidden = relu(h1 @ w1^T + b1) ----
    if (tid < 256) {
        int ff = tid & 63;
        int mq = tid >> 6;
        const float2* w1p = reinterpret_cast<const float2*>(w1 + ff * HID);
#pragma unroll
        for (int j = 0; j < 4; j++) {
            int m = mq + j * 4;
            float s = b1[ff];
            const uint32_t* hp = h1e + cur * MROWS * HSTR + m * HSTR;
#pragma unroll 8
            for (int p = 0; p < 64; p++) {
                float2 hv = __bfloat1622float2(
                    *reinterpret_cast<const __nv_bfloat162*>(&hp[p]));
                float2 wv = w1p[p];
                s = fmaf(hv.x, wv.x, s);
                s = fmaf(hv.y, wv.y, s);
            }
            hid_s[m * 64 + ff] = fmaxf(s, 0.f);
        }
    }
    __syncthreads();

    // ---- head: out = hidden @ w2^T + b2 ----
    if (tid < 32) {
        int m = tid >> 1, o = tid & 1;
        float s = b2[o];
#pragma unroll 8
        for (int k = 0; k < 64; k++)
            s = fmaf(hid_s[m * 64 + k], w2[o * 64 + k], s);
        out[(B0 + m) * 2 + o] = s;
    }
}

extern "C" void kernel_launch(void* const* d_in, const int* in_sizes, int n_in,
                              void* d_out, int out_size)
{
    const float* hr   = (const float*)d_in[0];
    const float* glu  = (const float*)d_in[1];
    const float* wih0 = (const float*)d_in[2];
    const float* whh0 = (const float*)d_in[3];
    const float* bih0 = (const float*)d_in[4];
    const float* bhh0 = (const float*)d_in[5];
    const float* wih1 = (const float*)d_in[6];
    const float* whh1 = (const float*)d_in[7];
    const float* bih1 = (const float*)d_in[8];
    const float* bhh1 = (const float*)d_in[9];
    const float* w1   = (const float*)d_in[10];
    const float* b1   = (const float*)d_in[11];
    const float* w2   = (const float*)d_in[12];
    const float* b2   = (const float*)d_in[13];
    float* out = (float*)d_out;

    cudaFuncSetAttribute(lstm_main, cudaFuncAttributeMaxDynamicSharedMemorySize, SMEM_SZ);

    prep_kernel<<<128, 256>>>(whh0, wih0, bih0, bhh0, wih1, whh1, bih1, bhh1);
    lstm_main<<<NCTA, NTHR, SMEM_SZ>>>(hr, glu, w1, b1, w2, b2, out);
}

// round 11
// speedup vs baseline: 1.8063x; 1.0183x over previous
#include <cuda_runtime.h>
#include <cuda_bf16.h>
#include <cstdint>

// LSTMBaseline: 2-layer LSTM (B=2048, T=512, H=128, in=2) + MLP head -> [B,2]
// bf16 mma.m16n8k16, 128 CTAs x 512 thr, M=16 batch rows/CTA.
// Round 11 = Round 10 + x-columns moved from mma (kp8 chunk, 87.5% zeros) to
// a scalar fp32 FFMA path. Freed 16KB of smem -> L1C 4->5 (one more resident
// layer-1 chunk, streamed 12->11). HSTR 76->68 (still ldmatrix conflict-free)
// to fit; dynamic smem at the 232448B ceiling.

#define T_STEPS 512
#define HID     128
#define MROWS   16
#define NCTA    128
#define NTHR    512
#define HSTR    68            // h-row stride in bf16-pairs; 68%32=4 -> conflict-free
#define PB      (MROWS * HSTR * 4)   // phase stride in bytes

#define L0KP    8             // layer0 k-chunks (128 h; x handled by FFMA path)
#define L1KP    16            // layer1 k-chunks (128 h0 | 128 h1)
#define L1C     5             // layer1 k-chunks cached in smem
#define NSTREAM (L1KP - L1C)  // 11 streamed k-chunks

// uint4 = {gtA.b0, gtA.b1, gtB.b0, gtB.b1}, gtA=2p, gtB=2p+1
// index: ((w*KP + kp)*2 + p)*32 + lane
__device__ uint4 d_WB0u[16 * L0KP * 2 * 32];   // 131072 B
__device__ uint4 d_WB1u[16 * L1KP * 2 * 32];   // 262144 B
__device__ uint4 d_XW0[128];                   // x-weights: (w*4+c0)*2+q, bf16 pairs
__device__ float d_B0[512];
__device__ float d_B1[512];

__device__ __forceinline__ uint32_t pack_bf2(float a, float b)
{
    __nv_bfloat162 p = __floats2bfloat162_rn(a, b);
    return *reinterpret_cast<uint32_t*>(&p);
}

__global__ void prep_kernel(const float* __restrict__ w_hh0, const float* __restrict__ w_ih0,
                            const float* __restrict__ b_ih0, const float* __restrict__ b_hh0,
                            const float* __restrict__ w_ih1, const float* __restrict__ w_hh1,
                            const float* __restrict__ b_ih1, const float* __restrict__ b_hh1)
{
    int idx = blockIdx.x * blockDim.x + threadIdx.x;
    int l = idx & 31, c = l & 3;
    int r = idx >> 5;

    if (idx < 16 * L0KP * 2 * 32) {           // ---- WB0 (pure w_hh0, K=128) ----
        int p = r & 1, rr = r >> 1;
        int kp = rr % L0KP, w = rr / L0KP;
        int n = w * 8 + (l >> 2);
        float v[2][4];
#pragma unroll
        for (int j = 0; j < 2; j++) {
            int g = (2 * p + j) * 128 + n;
#pragma unroll
            for (int q = 0; q < 4; q++) {
                int k = kp * 16 + (q >> 1) * 8 + c * 2 + (q & 1);
                v[j][q] = w_hh0[g * 128 + k];
            }
        }
        d_WB0u[idx] = make_uint4(
            pack_bf2(v[0][0], v[0][1]), pack_bf2(v[0][2], v[0][3]),
            pack_bf2(v[1][0], v[1][1]), pack_bf2(v[1][2], v[1][3]));
    }
    if (idx < 16 * L1KP * 2 * 32) {           // ---- WB1 (K=256: h0|h1) ----
        int p = r & 1, rr = r >> 1;
        int kp = rr % L1KP, w = rr / L1KP;
        int n = w * 8 + (l >> 2);
        const float* src = (kp < 8) ? w_ih1 : w_hh1;
        float v[2][4];
#pragma unroll
        for (int j = 0; j < 2; j++) {
            int g = (2 * p + j) * 128 + n;
#pragma unroll
            for (int q = 0; q < 4; q++) {
                int kk = (kp & 7) * 16 + (q >> 1) * 8 + c * 2 + (q & 1);
                v[j][q] = src[g * 128 + kk];
            }
        }
        d_WB1u[idx] = make_uint4(
            pack_bf2(v[0][0], v[0][1]), pack_bf2(v[0][2], v[0][3]),
            pack_bf2(v[1][0], v[1][1]), pack_bf2(v[1][2], v[1][3]));
    }
    if (idx < 64) {                           // ---- XW0: w_ih0 bf16-pair table ----
        int w = idx >> 2, c0 = idx & 3;
        uint32_t pr[8];
#pragma unroll
        for (int gt = 0; gt < 4; gt++)
#pragma unroll
            for (int j = 0; j < 2; j++) {
                int g = gt * 128 + w * 8 + 2 * c0 + j;
                pr[gt * 2 + j] = pack_bf2(w_ih0[g * 2 + 0], w_ih0[g * 2 + 1]);
            }
        d_XW0[idx * 2 + 0] = make_uint4(pr[0], pr[1], pr[2], pr[3]);
        d_XW0[idx * 2 + 1] = make_uint4(pr[4], pr[5], pr[6], pr[7]);
    }
    if (idx < 512) {
        d_B0[idx] = b_ih0[idx] + b_hh0[idx];
        d_B1[idx] = b_ih1[idx] + b_hh1[idx];
    }
}

__device__ __forceinline__ void mma16(float acc[4], uint32_t a0, uint32_t a1,
                                      uint32_t a2, uint32_t a3, uint32_t b0, uint32_t b1)
{
    asm volatile(
        "mma.sync.aligned.m16n8k16.row.col.f32.bf16.bf16.f32 "
        "{%0,%1,%2,%3}, {%4,%5,%6,%7}, {%8,%9}, {%0,%1,%2,%3};\n"
        : "+f"(acc[0]), "+f"(acc[1]), "+f"(acc[2]), "+f"(acc[3])
        : "r"(a0), "r"(a1), "r"(a2), "r"(a3), "r"(b0), "r"(b1));
}

#define LDSM4(a0, a1, a2, a3, addr)                                       \
    asm volatile("ldmatrix.sync.aligned.m8n8.x4.shared.b16 "              \
                 "{%0,%1,%2,%3}, [%4];"                                   \
                 : "=r"(a0), "=r"(a1), "=r"(a2), "=r"(a3) : "r"(addr))

__device__ __forceinline__ float tanha(float x)
{
    float y;
    asm("tanh.approx.f32 %0, %1;" : "=f"(y) : "f"(x));
    return y;
}
__device__ __forceinline__ float sigf(float x)
{
    return fmaf(tanha(0.5f * x), 0.5f, 0.5f);
}

__device__ __forceinline__ void mma4(float acc[4][4], uint32_t a0, uint32_t a1,
                                     uint32_t a2, uint32_t a3, uint4 w01, uint4 w23)
{
    mma16(acc[0], a0, a1, a2, a3, w01.x, w01.y);
    mma16(acc[1], a0, a1, a2, a3, w01.z, w01.w);
    mma16(acc[2], a0, a1, a2, a3, w23.x, w23.y);
    mma16(acc[3], a0, a1, a2, a3, w23.z, w23.w);
}

__device__ __forceinline__ void acc_init(float acc[4][4], const float* bs)
{
#pragma unroll
    for (int gt = 0; gt < 4; gt++) {
        acc[gt][0] = bs[gt * 2];  acc[gt][1] = bs[gt * 2 + 1];
        acc[gt][2] = bs[gt * 2];  acc[gt][3] = bs[gt * 2 + 1];
    }
}

__device__ __forceinline__ float2 unp_bf2(uint32_t u)
{
    return __bfloat1622float2(*reinterpret_cast<const __nv_bfloat162*>(&u));
}

// scalar x-projection: acc0 += x(row) . w_ih0, rows (r0, r0+8), 8 gate cols
__device__ __forceinline__ void xproj(float acc[4][4],
                                      const uint32_t* __restrict__ h0cur32,
                                      const uint4* __restrict__ sxw,
                                      int r0, int c0, int w)
{
    float2 x0 = unp_bf2(h0cur32[r0 * HSTR + 64]);         // (xr, xg) row r0
    float2 x1 = unp_bf2(h0cur32[(r0 + 8) * HSTR + 64]);   // row r0+8
    uint4 xa = sxw[(w * 4 + c0) * 2 + 0];
    uint4 xb = sxw[(w * 4 + c0) * 2 + 1];
    const uint32_t* xw = &xa.x;   // xa,xb contiguous in regs is not guaranteed;
    // unpack explicitly instead:
    uint32_t pr[8] = {xa.x, xa.y, xa.z, xa.w, xb.x, xb.y, xb.z, xb.w};
#pragma unroll
    for (int gt = 0; gt < 4; gt++)
#pragma unroll
        for (int j = 0; j < 2; j++) {
            float2 wv = unp_bf2(pr[gt * 2 + j]);
            acc[gt][0 + j] = fmaf(x0.x, wv.x, fmaf(x0.y, wv.y, acc[gt][0 + j]));
            acc[gt][2 + j] = fmaf(x1.x, wv.x, fmaf(x1.y, wv.y, acc[gt][2 + j]));
        }
    (void)xw;
}

__device__ __forceinline__ void cell(const float acc[4][4], float* cs,
                                     uint32_t* __restrict__ hdst, int r0, int c0, int w)
{
#pragma unroll
    for (int rg = 0; rg < 2; rg++) {
        float hv[2];
#pragma unroll
        for (int j = 0; j < 2; j++) {
            int idx = rg * 2 + j;
            float i_ = sigf(acc[0][idx]);
            float f_ = sigf(acc[1][idx]);
            float g_ = tanha(acc[2][idx]);
            float o_ = sigf(acc[3][idx]);
            float cv = fmaf(f_, cs[idx], i_ * g_);
            cs[idx] = cv;
            hv[j] = o_ * tanha(cv);
        }
        hdst[(r0 + 8 * rg) * HSTR + w * 4 + c0] = pack_bf2(hv[0], hv[1]);
    }
}

#define SW0_U4 (16 * L0KP * 2 * 32)           // 8192 uint4  = 131072 B
#define SW1_U4 (16 * L1C * 2 * 32)            // 5120 uint4  = 81920 B
#define HBUF   (2 * MROWS * HSTR)             // 2176 uint32 per layer pair
#define SMEM_SZ (SW0_U4 * 16 + SW1_U4 * 16 + 2048 + 2 * HBUF * 4)  // 232448 B

__global__ void __launch_bounds__(NTHR, 1)
lstm_main(const float* __restrict__ hr, const float* __restrict__ glu,
          const float* __restrict__ w1, const float* __restrict__ b1,
          const float* __restrict__ w2, const float* __restrict__ b2,
          float* __restrict__ out)
{
    extern __shared__ char smem_raw[];
    uint4*    sw0 = reinterpret_cast<uint4*>(smem_raw);
    uint4*    sw1 = reinterpret_cast<uint4*>(smem_raw + SW0_U4 * 16);
    uint4*    sxw = reinterpret_cast<uint4*>(smem_raw + SW0_U4 * 16 + SW1_U4 * 16);
    uint32_t* h0e = reinterpret_cast<uint32_t*>(smem_raw + SW0_U4 * 16 + SW1_U4 * 16 + 2048);
    uint32_t* h1e = h0e + HBUF;
    float*    hid_s = reinterpret_cast<float*>(smem_raw);   // overlay after loop

    const int tid = threadIdx.x;
    const int l = tid & 31, w = tid >> 5;
    const int r0 = l >> 2, c0 = l & 3;
    const int B0 = blockIdx.x * MROWS;

    // ---- load resident weights ----
    for (int i = tid; i < SW0_U4; i += NTHR) sw0[i] = d_WB0u[i];
    for (int i = tid; i < SW1_U4; i += NTHR) {
        int ll = i & 31, r = i >> 5;
        int p = r & 1, rr = r >> 1;
        int kp = rr % L1C, ww = rr / L1C;
        sw1[i] = d_WB1u[((ww * L1KP + kp) * 2 + p) * 32 + ll];
    }
    if (tid < 128) sxw[tid] = d_XW0[tid];
    for (int i = tid; i < HBUF; i += NTHR) { h0e[i] = 0u; h1e[i] = 0u; }
    __syncthreads();
    if (tid < MROWS)    // x_0 -> pair 64 of h0e phase 0
        h0e[tid * HSTR + 64] = pack_bf2(hr[(B0 + tid) * T_STEPS], glu[(B0 + tid) * T_STEPS]);

    float bs0[8], bs1[8];
#pragma unroll
    for (int gt = 0; gt < 4; gt++)
#pragma unroll
        for (int j = 0; j < 2; j++) {
            int g = gt * 128 + w * 8 + 2 * c0 + j;
            bs0[gt * 2 + j] = d_B0[g];
            bs1[gt * 2 + j] = d_B1[g];
        }

    float cs0[4] = {0.f, 0.f, 0.f, 0.f};
    float cs1[4] = {0.f, 0.f, 0.f, 0.f};

    // per-thread ldmatrix address offset
    const uint32_t aoff = (uint32_t)((l & 15) * (HSTR * 4) + ((l >> 4) << 4));
    const uint32_t h0u = (uint32_t)__cvta_generic_to_shared(h0e) + aoff;
    const uint32_t h1u = (uint32_t)__cvta_generic_to_shared(h1e) + aoff;

    const uint4* ws0 = sw0 + (w * L0KP) * 64 + l;             // [kp*64 + p*32]
    const uint4* ws1 = sw1 + (w * L1C) * 64 + l;
    const uint4* wg1 = d_WB1u + ((w * L1KP + L1C) * 2) * 32 + l;   // streamed s: [s*64 + p*32]

    __syncthreads();

    // ---- prologue: h0_0 from [h0=0, x_0] ----
    {
        float acc0[4][4];
        acc_init(acc0, bs0);
#pragma unroll
        for (int kp = 0; kp < L0KP; kp++) {
            uint32_t a0, a1, a2, a3;
            LDSM4(a0, a1, a2, a3, h0u + kp * 32);
            mma4(acc0, a0, a1, a2, a3, ws0[kp * 64], ws0[kp * 64 + 32]);
        }
        xproj(acc0, h0e, sxw, r0, c0, w);
        cell(acc0, cs0, h0e + MROWS * HSTR, r0, c0, w);
        if (tid < MROWS)
            h0e[MROWS * HSTR + tid * HSTR + 64] =
                pack_bf2(hr[(B0 + tid) * T_STEPS + 1], glu[(B0 + tid) * T_STEPS + 1]);
        __syncthreads();
    }

    int cur = 1;
#pragma unroll 1
    for (int t = 0; t < T_STEPS; t++) {
        const int nxt = cur ^ 1;
        const uint32_t* h0cur32 = h0e + cur * MROWS * HSTR;   // h0_t (+ x_{t+1})
        const uint32_t h0b = h0u + cur * PB;
        const uint32_t h1b = h1u + cur * PB;                  // h1_{t-1}
        float acc1[4][4], acc0[4][4];
        acc_init(acc1, bs1);
        acc_init(acc0, bs0);

        uint4 Wc0 = __ldg(wg1), Wc1 = __ldg(wg1 + 32);

        // ---- merged h0 pass: layer1 (all 8 kp) + layer0 (all 8 kp) ----
#pragma unroll
        for (int kp = 0; kp < 8; kp++) {
            uint32_t a0, a1, a2, a3;
            LDSM4(a0, a1, a2, a3, h0b + kp * 32);
            if (kp < L1C) {
                mma4(acc1, a0, a1, a2, a3, ws1[kp * 64], ws1[kp * 64 + 32]);
            } else {
                uint4 w01 = Wc0, w23 = Wc1;
                int s = kp - L1C;                       // 0..2
                Wc0 = __ldg(wg1 + (s + 1) * 64);
                Wc1 = __ldg(wg1 + (s + 1) * 64 + 32);
                mma4(acc1, a0, a1, a2, a3, w01, w23);
            }
            mma4(acc0, a0, a1, a2, a3, ws0[kp * 64], ws0[kp * 64 + 32]);
        }

        // ---- x-projection (fp32 FFMA, replaces the old kp8 mma chunk) ----
        xproj(acc0, h0cur32, sxw, r0, c0, w);

        // ---- cell0 (MUFU) issues under the h1-part tensor stream ----
        cell(acc0, cs0, h0e + nxt * MROWS * HSTR, r0, c0, w);   // h0_{t+1}
        if (tid < MROWS && t + 2 < T_STEPS)
            h0e[nxt * MROWS * HSTR + tid * HSTR + 64] =
                pack_bf2(hr[(B0 + tid) * T_STEPS + t + 2],
                         glu[(B0 + tid) * T_STEPS + t + 2]);

        // ---- h1 pass: layer1 kp 8..15 (streamed s = 3..10) ----
#pragma unroll
        for (int kp = 0; kp < 8; kp++) {
            uint32_t a0, a1, a2, a3;
            LDSM4(a0, a1, a2, a3, h1b + kp * 32);
            uint4 w01 = Wc0, w23 = Wc1;
            int s = 3 + kp;
            if (s + 1 < NSTREAM) {
                Wc0 = __ldg(wg1 + (s + 1) * 64);
                Wc1 = __ldg(wg1 + (s + 1) * 64 + 32);
            }
            mma4(acc1, a0, a1, a2, a3, w01, w23);
        }

        cell(acc1, cs1, h1e + nxt * MROWS * HSTR, r0, c0, w);   // h1_t

        __syncthreads();
        cur = nxt;
    }
    // final h1_511 in h1e phase cur; smem weights now dead.

    // ---- head: hidden = relu(h1 @ w1^T + b1) ----
    if (tid < 256) {
        int ff = tid & 63;
        int mq = tid >> 6;
        const float2* w1p = reinterpret_cast<const float2*>(w1 + ff * HID);
#pragma unroll
        for (int j = 0; j < 4; j++) {
            int m = mq + j * 4;
            float s = b1[ff];
            const uint32_t* hp = h1e + cur * MROWS * HSTR + m * HSTR;
#pragma unroll 8
            for (int p = 0; p < 64; p++) {
                float2 hv = unp_bf2(hp[p]);
                float2 wv = w1p[p];
                s = fmaf(hv.x, wv.x, s);
                s = fmaf(hv.y, wv.y, s);
            }
            hid_s[m * 64 + ff] = fmaxf(s, 0.f);
        }
    }
    __syncthreads();

    // ---- head: out = hidden @ w2^T + b2 ----
    if (tid < 32) {
        int m = tid >> 1, o = tid & 1;
        float s = b2[o];
#pragma unroll 8
        for (int k = 0; k < 64; k++)
            s = fmaf(hid_s[m * 64 + k], w2[o * 64 + k], s);
        out[(B0 + m) * 2 + o] = s;
    }
}

extern "C" void kernel_launch(void* const* d_in, const int* in_sizes, int n_in,
                              void* d_out, int out_size)
{
    const float* hr   = (const float*)d_in[0];
    const float* glu  = (const float*)d_in[1];
    const float* wih0 = (const float*)d_in[2];
    const float* whh0 = (const float*)d_in[3];
    const float* bih0 = (const float*)d_in[4];
    const float* bhh0 = (const float*)d_in[5];
    const float* wih1 = (const float*)d_in[6];
    const float* whh1 = (const float*)d_in[7];
    const float* bih1 = (const float*)d_in[8];
    const float* bhh1 = (const float*)d_in[9];
    const float* w1   = (const float*)d_in[10];
    const float* b1   = (const float*)d_in[11];
    const float* w2   = (const float*)d_in[12];
    const float* b2   = (const float*)d_in[13];
    float* out = (float*)d_out;

    cudaFuncSetAttribute(lstm_main, cudaFuncAttributeMaxDynamicSharedMemorySize, SMEM_SZ);

    prep_kernel<<<128, 256>>>(whh0, wih0, bih0, bhh0, wih1, whh1, bih1, bhh1);
    lstm_main<<<NCTA, NTHR, SMEM_SZ>>>(hr, glu, w1, b1, w2, b2, out);
}